// round 6
// baseline (speedup 1.0000x reference)
#include <cuda_runtime.h>
#include <cuda_bf16.h>

#define BB 16
#define EE 128
#define CC 512
#define RSQRTC 0.044194173824159216f   // 1/sqrt(512)

__device__ float  g_G[BB * EE * EE];   // Gram matrices, 1 MB
__device__ double g_stats[2];          // sum, sumsq of masked sq_dist
__device__ int    g_lab64;             // 1 if labels are int64, 0 if int32

// ---------- f32x2 packed helpers (ptxas won't auto-fuse FFMA2) ----------
__device__ __forceinline__ unsigned long long f2_pack(float x, float y) {
    unsigned long long r;
    asm("mov.b64 %0, {%1, %2};" : "=l"(r) : "f"(x), "f"(y));
    return r;
}
__device__ __forceinline__ float2 f2_unpack(unsigned long long v) {
    float2 p;
    asm("mov.b64 {%0, %1}, %2;" : "=f"(p.x), "=f"(p.y) : "l"(v));
    return p;
}
__device__ __forceinline__ unsigned long long f2_fma(unsigned long long a,
                                                     unsigned long long b,
                                                     unsigned long long c) {
    unsigned long long d;
    asm("fma.rn.f32x2 %0, %1, %2, %3;" : "=l"(d) : "l"(a), "l"(b), "l"(c));
    return d;
}
__device__ __forceinline__ unsigned long long f2_mul(unsigned long long a,
                                                     unsigned long long b) {
    unsigned long long d;
    asm("mul.rn.f32x2 %0, %1, %2;" : "=l"(d) : "l"(a), "l"(b));
    return d;
}

// =====================================================================
// K_A: batched G[b] = X_b * X_b^T   (32x64 output tile per CTA)
//      block(16,8)=128 thr, each thread 4x4 micro-tile, k-tile 32.
//      Block (0,0,0) additionally zeroes stats + detects label dtype.
// =====================================================================
__global__ void k_gram(const float* __restrict__ x, const int* __restrict__ lab32) {
    __shared__ float As[32][33];   // [kk][row]
    __shared__ float Bs[32][65];   // [kk][col]
    __shared__ int   s_nz;

    const int b  = blockIdx.z;
    const int i0 = blockIdx.x * 32;
    const int j0 = blockIdx.y * 64;
    const int tx = threadIdx.x;            // 0..15
    const int ty = threadIdx.y;            // 0..7
    const int tid = ty * 16 + tx;          // 0..127

    if (blockIdx.x == 0 && blockIdx.y == 0 && blockIdx.z == 0) {
        // label dtype detection: first 8192 bytes are valid in both layouts.
        // (int64 labels in [0,5] -> all high words zero; int32 labels make
        //  odd words nonzero with overwhelming probability over 1024 samples)
        if (tid == 0) s_nz = 0;
        __syncthreads();
        int nz = 0;
        for (int k = tid; k < 1024; k += 128)
            if (lab32[2 * k + 1] != 0) nz = 1;
        if (nz) atomicOr(&s_nz, 1);
        __syncthreads();
        if (tid == 0) {
            g_lab64 = s_nz ? 0 : 1;
            g_stats[0] = 0.0;
            g_stats[1] = 0.0;
        }
    }

    const float* xb = x + (size_t)b * EE * CC;
    float acc[4][4] = {};

    for (int k0 = 0; k0 < CC; k0 += 32) {
        for (int e = tid; e < 32 * 32; e += 128) {
            int r = e >> 5, kk = e & 31;
            As[kk][r] = xb[(i0 + r) * CC + k0 + kk];
        }
        for (int e = tid; e < 64 * 32; e += 128) {
            int ccol = e >> 5, kk = e & 31;
            Bs[kk][ccol] = xb[(j0 + ccol) * CC + k0 + kk];
        }
        __syncthreads();
        #pragma unroll
        for (int kk = 0; kk < 32; kk++) {
            float a[4], bb[4];
            #pragma unroll
            for (int u = 0; u < 4; u++) a[u] = As[kk][ty * 4 + u];
            #pragma unroll
            for (int v = 0; v < 4; v++) bb[v] = Bs[kk][tx * 4 + v];
            #pragma unroll
            for (int u = 0; u < 4; u++)
                #pragma unroll
                for (int v = 0; v < 4; v++)
                    acc[u][v] += a[u] * bb[v];
        }
        __syncthreads();
    }

    // STG.128: j0 + tx*4 is 4-aligned, v-contiguous
    float* Gb = g_G + b * EE * EE;
    #pragma unroll
    for (int u = 0; u < 4; u++) {
        float4 vv = make_float4(acc[u][0], acc[u][1], acc[u][2], acc[u][3]);
        *(float4*)&Gb[(i0 + ty * 4 + u) * EE + (j0 + tx * 4)] = vv;
    }
}

// =====================================================================
// K_B: masked mean/var statistics of sq_dist (recomputed from G).
//      Double accumulation, block reduce, atomicAdd.
// =====================================================================
__global__ void k_stats() {
    double s = 0.0, s2 = 0.0;
    const int total = BB * EE * EE;
    for (int idx = blockIdx.x * blockDim.x + threadIdx.x; idx < total;
         idx += gridDim.x * blockDim.x) {
        int j = idx & 127;
        int i = (idx >> 7) & 127;
        if (i == j) continue;
        const float* Gb = g_G + (idx >> 14 << 14);
        float sd = (Gb[i * 129] + Gb[j * 129] - 2.0f * Gb[idx & 16383]) * RSQRTC;
        s  += (double)sd;
        s2 += (double)sd * (double)sd;
    }
    __shared__ double sh[256], sh2[256];
    int t = threadIdx.x;
    sh[t] = s; sh2[t] = s2;
    __syncthreads();
    for (int o = 128; o > 0; o >>= 1) {
        if (t < o) { sh[t] += sh[t + o]; sh2[t] += sh2[t + o]; }
        __syncthreads();
    }
    if (t == 0) {
        atomicAdd(&g_stats[0], sh[0]);
        atomicAdd(&g_stats[1], sh2[0]);
    }
}

// =====================================================================
// K_E: per-batch CTA (1024 thr):
//   weights -> row sums -> M = I - 0.2 S  (registers, f32x2-packed)
//   -> Gauss-Jordan (no pivoting: M diag-dominant) -> inverse
//   -> L1 row norm, per-class sums over labels, log output.
// Thread layout: tid = chunk*128 + row; chunk 0..7 owns 32 columns
// of its row (0..3: left/M half, 4..7: right/identity half).
// =====================================================================
#define SMEM_E_FLOATS 21252
#define SMEM_E_BYTES  (SMEM_E_FLOATS * 4)

__global__ __launch_bounds__(1024, 1) void k_solve(const void* __restrict__ labels,
                                                   float* __restrict__ out) {
    extern __shared__ float sm[];
    float (*sG)[129]   = (float (*)[129])sm;      //      0 .. 16512
    float* pivrow      = sm + 16512;              // [2][256]
    float* multbuf     = sm + 17024;              // [2][128]
    float* srinv       = sm + 17280;              // [128]
    float* sdiag       = sm + 17408;              // [128]
    float* spart       = sm + 17536;              // [4*128]
    float* sl1         = sm + 18048;              // [4*128]
    float* scls        = sm + 18560;              // [4*128*5]
    int*   slab        = (int*)(sm + 21120);      // [128]
    float* s_rstd      = sm + 21248;

    const int tid   = threadIdx.x;
    const int chunk = tid >> 7;        // 0..7 (uniform per warp)
    const int row   = tid & 127;
    const int b     = blockIdx.x;

    // --- load G[b] into smem: LDG.128 (4 consecutive floats always within
    //     one 128-float row since 128 % 4 == 0; pitch-129 only shifts rows) ---
    const float* Gb = g_G + b * 16384;
    for (int i = tid * 4; i < 16384; i += 4096) {
        float4 v = *(const float4*)&Gb[i];
        float* d = &sG[i >> 7][i & 127];
        d[0] = v.x; d[1] = v.y; d[2] = v.z; d[3] = v.w;
    }
    __syncthreads();

    if (tid < 128) {
        sdiag[tid] = sG[tid][tid];
        int lb;
        if (g_lab64) lb = (int)((const long long*)labels)[b * EE + tid];
        else         lb = ((const int*)labels)[b * EE + tid];
        slab[tid] = lb;
    }
    if (tid == 0) {
        double s = g_stats[0], s2 = g_stats[1];
        double cnt = (double)(BB * EE * (EE - 1));
        double mean = s / cnt;
        double var = (s2 - cnt * mean * mean) / (cnt - 1.0);
        s_rstd[0] = (float)(1.0 / sqrt(var));
    }
    __syncthreads();

    const float coef = RSQRTC * s_rstd[0];

    // --- weights (in place over sG) + row-sum partials ---
    if (chunk < 4) {
        float di = sdiag[row];
        float rpart = 0.f;
        #pragma unroll
        for (int c = 0; c < 32; c++) {
            int col = chunk * 32 + c;
            float w = 0.f;
            if (col != row)
                w = expf(-(di + sdiag[col] - 2.0f * sG[row][col]) * coef);
            sG[row][col] = w;
            rpart += w;
        }
        spart[chunk * 128 + row] = rpart;
    }
    __syncthreads();
    if (tid < 128) {
        float rs = spart[tid] + spart[128 + tid] + spart[256 + tid] + spart[384 + tid];
        srinv[tid] = 0.2f / (1e-4f + rs);   // alpha folded in
    }
    __syncthreads();

    // --- build augmented [M | I] in registers (f32x2-packed) ---
    unsigned long long A2[16];
    if (chunk < 4) {
        #pragma unroll
        for (int k = 0; k < 16; k++) {
            int c0 = chunk * 32 + 2 * k, c1 = c0 + 1;
            float m0 = ((c0 == row) ? 1.f : 0.f) - sG[row][c0] * srinv[c0];
            float m1 = ((c1 == row) ? 1.f : 0.f) - sG[row][c1] * srinv[c1];
            A2[k] = f2_pack(m0, m1);
        }
    } else {
        int base = (chunk - 4) * 32;
        #pragma unroll
        for (int k = 0; k < 16; k++) {
            float m0 = (base + 2 * k     == row) ? 1.f : 0.f;
            float m1 = (base + 2 * k + 1 == row) ? 1.f : 0.f;
            A2[k] = f2_pack(m0, m1);
        }
    }

    // pre-write multipliers for p=0 (column 0 lives in chunk 0)
    if (chunk == 0) {
        float2 t = f2_unpack(A2[0]);
        multbuf[row] = t.x;
    }
    __syncthreads();

    // --- Gauss-Jordan, double-buffered pivot row/multipliers: 2 bars/step ---
    #pragma unroll 1
    for (int p = 0; p < 128; p++) {
        const int buf = p & 1;
        // scale pivot row, publish it
        if (row == p) {
            float rp = 1.0f / multbuf[buf * 128 + p];
            unsigned long long rp2 = f2_pack(rp, rp);
            float* pr = &pivrow[buf * 256 + chunk * 32];
            #pragma unroll
            for (int k = 0; k < 16; k++) {
                A2[k] = f2_mul(A2[k], rp2);
                *(unsigned long long*)(pr + 2 * k) = A2[k];
            }
        }
        __syncthreads();
        // eliminate
        if (row != p) {
            float m = multbuf[buf * 128 + row];
            unsigned long long nm2 = f2_pack(-m, -m);
            const float* pr = &pivrow[buf * 256 + chunk * 32];
            #pragma unroll
            for (int k = 0; k < 16; k += 2) {
                ulonglong2 pv = *(const ulonglong2*)(pr + 2 * k);
                A2[k]     = f2_fma(pv.x, nm2, A2[k]);
                A2[k + 1] = f2_fma(pv.y, nm2, A2[k + 1]);
            }
        }
        // publish next column's multipliers into the other buffer
        if (p < 127) {
            int pn = p + 1;
            if (chunk == (pn >> 5)) {
                int pcn = pn & 31;
                float2 t = f2_unpack(A2[pcn >> 1]);
                multbuf[(1 - buf) * 128 + row] = (pcn & 1) ? t.y : t.x;
            }
        }
        __syncthreads();
    }

    // --- epilogue: inverse lives in chunks 4..7 ---
    // Branch-free class accumulation (FSEL instead of BSSY chains) keeps the
    // live set small under the 64-reg cap of __launch_bounds__(1024,1).
    if (chunk >= 4) {
        int qc = chunk - 4;
        float l1 = 0.f, c0 = 0.f, c1 = 0.f, c2 = 0.f, c3 = 0.f, c4 = 0.f;
        #pragma unroll
        for (int k = 0; k < 16; k++) {
            float2 t = f2_unpack(A2[k]);
            int j0 = qc * 32 + 2 * k;
            l1 += fabsf(t.x) + fabsf(t.y);
            int lb0 = slab[j0], lb1 = slab[j0 + 1];
            c0 += (lb0 == 0 ? t.x : 0.f) + (lb1 == 0 ? t.y : 0.f);
            c1 += (lb0 == 1 ? t.x : 0.f) + (lb1 == 1 ? t.y : 0.f);
            c2 += (lb0 == 2 ? t.x : 0.f) + (lb1 == 2 ? t.y : 0.f);
            c3 += (lb0 == 3 ? t.x : 0.f) + (lb1 == 3 ? t.y : 0.f);
            c4 += (lb0 == 4 ? t.x : 0.f) + (lb1 == 4 ? t.y : 0.f);
        }
        sl1[qc * 128 + row] = l1;
        float* sc = &scls[(qc * 128 + row) * 5];
        sc[0] = c0; sc[1] = c1; sc[2] = c2; sc[3] = c3; sc[4] = c4;
    }
    __syncthreads();
    if (tid < 128) {
        float l1 = sl1[tid] + sl1[128 + tid] + sl1[256 + tid] + sl1[384 + tid];
        l1 = fmaxf(l1, 1e-12f);
        float inv = 1.0f / l1;
        #pragma unroll
        for (int k = 0; k < 5; k++) {
            float y = scls[tid * 5 + k] + scls[(128 + tid) * 5 + k] +
                      scls[(256 + tid) * 5 + k] + scls[(384 + tid) * 5 + k];
            out[(b * EE + tid) * 5 + k] = logf(y * inv + 1e-6f);
        }
    }
}

// =====================================================================
extern "C" void kernel_launch(void* const* d_in, const int* in_sizes, int n_in,
                              void* d_out, int out_size) {
    const float* x      = (const float*)d_in[0];
    const void*  labels = d_in[1];
    float*       out    = (float*)d_out;

    cudaFuncSetAttribute(k_solve, cudaFuncAttributeMaxDynamicSharedMemorySize,
                         SMEM_E_BYTES);

    dim3 gridA(4, 2, BB);     // 128 CTAs
    dim3 blockA(16, 8);
    k_gram<<<gridA, blockA>>>(x, (const int*)labels);
    k_stats<<<256, 256>>>();
    k_solve<<<BB, 1024, SMEM_E_BYTES>>>(labels, out);
}

// round 11
// speedup vs baseline: 9.3707x; 9.3707x over previous
#include <cuda_runtime.h>
#include <cuda_bf16.h>

#define BB 16
#define EE 128
#define CC 512
#define RSQRTC 0.044194173824159216f   // 1/sqrt(512)
#define NPARTS 4
#define PSTRIDE (BB * EE * EE)         // 262144
#define KITER 10

__device__ float  g_Gp[NPARTS * BB * EE * EE];  // 4 MB split-k partials
__device__ float  g_G[BB * EE * EE];            // 1 MB summed Gram
__device__ double g_stats[2];                    // sum, sumsq of masked sq_dist
__device__ int    g_lab64;                       // labels dtype flag

// =====================================================================
// K_A: split-k batched Gram partial: G_part[kp][b] = X_b[:, kp*128:+128] X^T
// grid (4,2,64): z = b*4 + kp. 32x64 tile, 128 thr, 4x4 micro, k-tile 32.
// float4 smem micro-loads (padded pitches keep 16B alignment).
// Block (0,0,0) zeroes stats + detects label dtype.
// =====================================================================
__global__ void k_gram(const float* __restrict__ x, const int* __restrict__ lab32) {
    __shared__ __align__(16) float As[32][36];   // [kk][row]
    __shared__ __align__(16) float Bs[32][68];   // [kk][col]
    __shared__ int s_nz;

    const int z  = blockIdx.z;
    const int b  = z >> 2;
    const int kp = z & 3;
    const int i0 = blockIdx.x * 32;
    const int j0 = blockIdx.y * 64;
    const int tx = threadIdx.x;            // 0..15
    const int ty = threadIdx.y;            // 0..7
    const int tid = ty * 16 + tx;          // 0..127

    if (blockIdx.x == 0 && blockIdx.y == 0 && z == 0) {
        // label dtype detection: first 8192 bytes valid in both layouts.
        if (tid == 0) s_nz = 0;
        __syncthreads();
        int nz = 0;
        for (int k = tid; k < 1024; k += 128)
            if (lab32[2 * k + 1] != 0) nz = 1;
        if (nz) atomicOr(&s_nz, 1);
        __syncthreads();
        if (tid == 0) {
            g_lab64 = s_nz ? 0 : 1;
            g_stats[0] = 0.0;
            g_stats[1] = 0.0;
        }
    }

    const float* xb = x + (size_t)b * EE * CC;
    float acc[4][4] = {};
    const int kbase = kp * 128;

    for (int k0 = kbase; k0 < kbase + 128; k0 += 32) {
        // float4 fills: As 256 vec (2/thr), Bs 512 vec (4/thr); coalesced LDG.128
        #pragma unroll
        for (int v = tid; v < 256; v += 128) {
            int r = v >> 3, kq = v & 7;
            float4 g = *(const float4*)&xb[(i0 + r) * CC + k0 + kq * 4];
            As[kq * 4 + 0][r] = g.x; As[kq * 4 + 1][r] = g.y;
            As[kq * 4 + 2][r] = g.z; As[kq * 4 + 3][r] = g.w;
        }
        #pragma unroll
        for (int v = tid; v < 512; v += 128) {
            int c = v >> 3, kq = v & 7;
            float4 g = *(const float4*)&xb[(j0 + c) * CC + k0 + kq * 4];
            Bs[kq * 4 + 0][c] = g.x; Bs[kq * 4 + 1][c] = g.y;
            Bs[kq * 4 + 2][c] = g.z; Bs[kq * 4 + 3][c] = g.w;
        }
        __syncthreads();
        #pragma unroll
        for (int kk = 0; kk < 32; kk++) {
            float4 a4 = *(const float4*)&As[kk][ty * 4];
            float4 b4 = *(const float4*)&Bs[kk][tx * 4];
            float av[4] = {a4.x, a4.y, a4.z, a4.w};
            float bv[4] = {b4.x, b4.y, b4.z, b4.w};
            #pragma unroll
            for (int u = 0; u < 4; u++)
                #pragma unroll
                for (int v = 0; v < 4; v++)
                    acc[u][v] += av[u] * bv[v];
        }
        __syncthreads();
    }

    float* Gp = g_Gp + kp * PSTRIDE + b * EE * EE;
    #pragma unroll
    for (int u = 0; u < 4; u++) {
        float4 vv = make_float4(acc[u][0], acc[u][1], acc[u][2], acc[u][3]);
        *(float4*)&Gp[(i0 + ty * 4 + u) * EE + (j0 + tx * 4)] = vv;
    }
}

// =====================================================================
// K_B: sum the 4 k-parts into g_G, compute global masked mean/var stats.
// Diagonals recomputed from parts (no dependence on g_G writes -> no race).
// =====================================================================
__global__ void k_stats() {
    double s = 0.0, s2 = 0.0;
    const int total = BB * EE * EE;
    const float* __restrict__ P = g_Gp;
    for (int idx = blockIdx.x * blockDim.x + threadIdx.x; idx < total;
         idx += gridDim.x * blockDim.x) {
        float g = P[idx] + P[idx + PSTRIDE] + P[idx + 2 * PSTRIDE] + P[idx + 3 * PSTRIDE];
        g_G[idx] = g;
        int j = idx & 127;
        int i = (idx >> 7) & 127;
        if (i != j) {
            int base = idx & ~16383;            // b*16384
            int di = base + i * 129, dj = base + j * 129;
            float gii = P[di] + P[di + PSTRIDE] + P[di + 2 * PSTRIDE] + P[di + 3 * PSTRIDE];
            float gjj = P[dj] + P[dj + PSTRIDE] + P[dj + 2 * PSTRIDE] + P[dj + 3 * PSTRIDE];
            float sd = (gii + gjj - 2.0f * g) * RSQRTC;
            s  += (double)sd;
            s2 += (double)sd * (double)sd;
        }
    }
    __shared__ double sh[256], sh2[256];
    int t = threadIdx.x;
    sh[t] = s; sh2[t] = s2;
    __syncthreads();
    for (int o = 128; o > 0; o >>= 1) {
        if (t < o) { sh[t] += sh[t + o]; sh2[t] += sh2[t + o]; }
        __syncthreads();
    }
    if (t == 0) {
        atomicAdd(&g_stats[0], sh[0]);
        atomicAdd(&g_stats[1], sh2[0]);
    }
}

// =====================================================================
// K_E: per-batch CTA (1024 thr). No matrix inversion:
//   P = inv(I - aS) applied to [onehot | 1] via Jacobi / Neumann:
//   v <- v0 + A v,  A = alpha*W*diag(1/(1e-4+rowsum)),  ||A||_1 < 0.2 always.
//   Ones-column yields L1 row norms (P >= 0 entrywise).
// W fully register-resident: thread (jblk=tid>>7, i=tid&127) owns W[i][16j].
// t reads are warp-uniform broadcasts; partials via pad-9 conflict-free smem.
// =====================================================================
__global__ __launch_bounds__(1024, 1) void k_solve(const void* __restrict__ labels,
                                                   float* __restrict__ out) {
    __shared__ __align__(16) float t[EE][8];      // u / final v, rows 32B
    __shared__ float part[6][EE][9];              // conflict-free partials
    __shared__ float sdiag[EE], srinv[EE];
    __shared__ int   slab[EE];
    __shared__ float scoef;

    const int tid  = threadIdx.x;
    const int jblk = tid >> 7;       // 0..7 (warp-uniform)
    const int i    = tid & 127;
    const int j0   = jblk * 16;
    const int b    = blockIdx.x;

    if (tid < 128) {
        sdiag[tid] = g_G[b * 16384 + tid * 129];
        int lb;
        if (g_lab64) lb = (int)((const long long*)labels)[b * EE + tid];
        else         lb = ((const int*)labels)[b * EE + tid];
        slab[tid] = lb;
    }
    if (tid == 0) {
        double s = g_stats[0], s2 = g_stats[1];
        double cnt = (double)(BB * EE * (EE - 1));
        double mean = s / cnt;
        double var = (s2 - cnt * mean * mean) / (cnt - 1.0);
        scoef = (float)(1.0 / sqrt(var)) * RSQRTC;
    }
    __syncthreads();

    // --- weights into registers + row-sum partials ---
    float w[16];
    {
        const float* Grow = g_G + b * 16384 + i * 128 + j0;
        float4 g0 = *(const float4*)&Grow[0];
        float4 g1 = *(const float4*)&Grow[4];
        float4 g2 = *(const float4*)&Grow[8];
        float4 g3 = *(const float4*)&Grow[12];
        float gv[16] = {g0.x, g0.y, g0.z, g0.w, g1.x, g1.y, g1.z, g1.w,
                        g2.x, g2.y, g2.z, g2.w, g3.x, g3.y, g3.z, g3.w};
        const float di = sdiag[i];
        const float coef = scoef;
        float rpart = 0.f;
        #pragma unroll
        for (int k = 0; k < 16; k++) {
            int j = j0 + k;
            float ww = 0.f;
            if (j != i)
                ww = expf(-(di + sdiag[j] - 2.0f * gv[k]) * coef);
            w[k] = ww;
            rpart += ww;
        }
        part[0][i][jblk] = rpart;
    }
    __syncthreads();
    if (tid < 128) {
        float rs = 0.f;
        #pragma unroll
        for (int jb = 0; jb < 8; jb++) rs += part[0][tid][jb];
        float sr = 0.2f / (1e-4f + rs);   // alpha folded in
        srinv[tid] = sr;
        int lb = slab[tid];
        #pragma unroll
        for (int c = 0; c < 5; c++) t[tid][c] = sr * ((lb == c) ? 1.f : 0.f);
        t[tid][5] = sr;                   // ones column
        t[tid][6] = 0.f; t[tid][7] = 0.f;
    }
    __syncthreads();

    // --- Jacobi iterations ---
    for (int it = 0; it < KITER; it++) {
        float a0 = 0.f, a1 = 0.f, a2 = 0.f, a3 = 0.f, a4 = 0.f, a5 = 0.f;
        #pragma unroll
        for (int k = 0; k < 16; k++) {
            float4 t03 = *(const float4*)&t[j0 + k][0];   // warp broadcast
            float2 t45 = *(const float2*)&t[j0 + k][4];
            float ww = w[k];
            a0 += ww * t03.x; a1 += ww * t03.y; a2 += ww * t03.z;
            a3 += ww * t03.w; a4 += ww * t45.x; a5 += ww * t45.y;
        }
        part[0][i][jblk] = a0; part[1][i][jblk] = a1; part[2][i][jblk] = a2;
        part[3][i][jblk] = a3; part[4][i][jblk] = a4; part[5][i][jblk] = a5;
        __syncthreads();
        if (tid < 768) {
            int ii = tid & 127, col = tid >> 7;
            float ssum = 0.f;
            #pragma unroll
            for (int jb = 0; jb < 8; jb++) ssum += part[col][ii][jb];
            int lb = slab[ii];
            float v0 = (col < 5) ? ((lb == col) ? 1.f : 0.f) : 1.f;
            float vnew = v0 + ssum;
            t[ii][col] = (it == KITER - 1) ? vnew : (srinv[ii] * vnew);
        }
        __syncthreads();
    }

    // --- output: log(v/l1 + eps) ---
    if (tid < 640) {
        int ii = tid / 5, c = tid % 5;
        float l1 = fmaxf(t[ii][5], 1e-12f);
        out[(b * EE + ii) * 5 + c] = logf(t[ii][c] / l1 + 1e-6f);
    }
}

// =====================================================================
extern "C" void kernel_launch(void* const* d_in, const int* in_sizes, int n_in,
                              void* d_out, int out_size) {
    const float* x      = (const float*)d_in[0];
    const void*  labels = d_in[1];
    float*       out    = (float*)d_out;

    dim3 gridA(4, 2, BB * NPARTS);   // 512 CTAs
    dim3 blockA(16, 8);
    k_gram<<<gridA, blockA>>>(x, (const int*)labels);
    k_stats<<<512, 256>>>();
    k_solve<<<BB, 1024>>>(labels, out);
}